// round 3
// baseline (speedup 1.0000x reference)
#include <cuda_runtime.h>
#include <math.h>

// Problem dims (fixed by setup_inputs)
#define BB 64
#define NN 4096
#define FF 256
#define NCLS 10
#define HID 64
#define ODIM 128

#define HASH_SZ 8192
#define HASH_MASK 8191
#define EMPTY_SLOT 0xFFFFFFFFu

// Scratch: transposed X [B, F, N] and per-(b,f) stats [B*F, 6]
__device__ float g_xt[(size_t)BB * FF * NN];     // 256 MB
__device__ float g_stats[(size_t)BB * FF * 6];

// ---------------------------------------------------------------------------
// Kernel A: transpose X [B, N, F] -> g_xt [B, F, N], coalesced both ways.
// ---------------------------------------------------------------------------
__global__ void __launch_bounds__(256) transpose_kernel(const float* __restrict__ X) {
    __shared__ float tile[32][33];
    const int b  = blockIdx.z;
    const int f0 = blockIdx.x * 32;
    const int n0 = blockIdx.y * 32;
    const int tx = threadIdx.x;   // 0..31
    const int ty = threadIdx.y;   // 0..7

    const float* Xb  = X    + (size_t)b * NN * FF;
    float*       Xtb = g_xt + (size_t)b * FF * NN;

#pragma unroll
    for (int k = 0; k < 4; k++) {
        tile[ty + k * 8][tx] = Xb[(size_t)(n0 + ty + k * 8) * FF + (f0 + tx)];
    }
    __syncthreads();
#pragma unroll
    for (int k = 0; k < 4; k++) {
        Xtb[(size_t)(f0 + ty + k * 8) * NN + (n0 + tx)] = tile[tx][ty + k * 8];
    }
}

// ---------------------------------------------------------------------------
// Kernel B: per-(b,f) column statistics.
// One 256-thread CTA per column; coalesced column load; shared hash set for
// exact distinct count; shuffle-tree reductions for the moments.
// ---------------------------------------------------------------------------
__device__ __forceinline__ float warp_sum(float v) {
#pragma unroll
    for (int o = 16; o > 0; o >>= 1) v += __shfl_down_sync(0xffffffffu, v, o);
    return v;
}
__device__ __forceinline__ float warp_max(float v) {
#pragma unroll
    for (int o = 16; o > 0; o >>= 1) v = fmaxf(v, __shfl_down_sync(0xffffffffu, v, o));
    return v;
}

__global__ void __launch_bounds__(256) stats_kernel(const long long* __restrict__ y) {
    const int f = blockIdx.x;
    const int b = blockIdx.y;
    const float*     col = g_xt + ((size_t)b * FF + f) * NN;
    const long long* yb  = y    + (size_t)b * NN;

    __shared__ unsigned s_hash[HASH_SZ];       // 32 KB
    __shared__ float    s_part[26][8];
    __shared__ float    s_final[26];

    const int tid = threadIdx.x;

    for (int i = tid; i < HASH_SZ; i += 256) s_hash[i] = EMPTY_SLOT;
    __syncthreads();

    // Front-batched coalesced loads: 16 values + 16 labels per thread.
    float v[16];
    int   yv[16];
#pragma unroll
    for (int i = 0; i < 16; i++) {
        const int n = i * 256 + tid;
        v[i]  = col[n];
        yv[i] = (int)yb[n];
    }

    float vsum = 0.f, vsq = 0.f, vabs = 0.f, vmax = 0.f;
    float nanc = 0.f, uniq = 0.f;
    float csum[NCLS];
    float ccnt[NCLS];
#pragma unroll
    for (int c = 0; c < NCLS; c++) { csum[c] = 0.f; ccnt[c] = 0.f; }

#pragma unroll 4
    for (int i = 0; i < 16; i++) {
        float x = v[i];
        if (isnan(x)) { nanc += 1.f; x = 0.f; }
        const float ax = fabsf(x);
        vsum += x; vsq += x * x; vabs += ax; vmax = fmaxf(vmax, ax);
        const int lab = yv[i];
#pragma unroll
        for (int c = 0; c < NCLS; c++) {
            if (lab == c) { csum[c] += x; ccnt[c] += 1.f; }
        }
        // distinct count: canonicalize -0 -> +0, insert into shared hash set
        unsigned bits = (x == 0.0f) ? 0u : __float_as_uint(x);
        unsigned h = (bits * 2654435761u) >> 19;   // top 13 bits -> [0, 8192)
        for (;;) {
            unsigned old = atomicCAS(&s_hash[h], EMPTY_SLOT, bits);
            if (old == EMPTY_SLOT) { uniq += 1.f; break; }
            if (old == bits) break;
            h = (h + 1) & HASH_MASK;
        }
    }

    // Block reduction of 26 quantities
    float vals[26];
    vals[0] = vsum; vals[1] = vsq; vals[2] = vabs; vals[3] = vmax;
    vals[4] = nanc; vals[5] = uniq;
#pragma unroll
    for (int c = 0; c < NCLS; c++) { vals[6 + c] = csum[c]; vals[16 + c] = ccnt[c]; }

    const int lane = tid & 31, w = tid >> 5;
#pragma unroll
    for (int q = 0; q < 26; q++) {
        float r = (q == 3) ? warp_max(vals[q]) : warp_sum(vals[q]);
        if (lane == 0) s_part[q][w] = r;
    }
    __syncthreads();
    if (tid < 26) {
        float r = s_part[tid][0];
#pragma unroll
        for (int ww = 1; ww < 8; ww++) {
            r = (tid == 3) ? fmaxf(r, s_part[tid][ww]) : (r + s_part[tid][ww]);
        }
        s_final[tid] = r;
    }
    __syncthreads();

    if (tid == 0) {
        const float invN = 1.0f / (float)NN;
        const float sum     = s_final[0];
        const float sumsq   = s_final[1];
        const float sumabs  = s_final[2];
        const float maxabs  = s_final[3];
        const float nancnt  = s_final[4];
        const float uniqcnt = s_final[5];

        const float mean     = sum * invN;
        float       variance = fmaxf(sumsq * invN - mean * mean, 0.0f);
        const float mean_abs = sumabs * invN;
        const float miss     = nancnt * invN;
        const float uratio   = uniqcnt * invN;

        float bv = 0.f;
#pragma unroll
        for (int c = 0; c < NCLS; c++) {
            const float cnt = s_final[16 + c];
            const float cm  = s_final[6 + c] / fmaxf(cnt, 1.0f);
            const float d   = cm - mean;
            bv += cnt * d * d;
        }
        bv *= invN;                                   // counts.sum == N
        float ts = bv / fmaxf(variance, 1e-6f);

        float st[6] = {ts, miss, uratio, variance, mean_abs, maxabs};
        float* o = g_stats + ((size_t)b * FF + f) * 6;
#pragma unroll
        for (int k = 0; k < 6; k++) o[k] = isfinite(st[k]) ? st[k] : 0.0f;
    }
}

// ---------------------------------------------------------------------------
// Kernel C: MLP  out = gelu(stats @ W1 + b1) @ W2 + b2, per (b,f) row.
// Weights staged in SMEM once per block; 2 rows in flight per 256-thread CTA.
// ---------------------------------------------------------------------------
__global__ void __launch_bounds__(256) mlp_kernel(
    const float* __restrict__ W1, const float* __restrict__ b1,
    const float* __restrict__ W2, const float* __restrict__ b2,
    float* __restrict__ out)
{
    __shared__ float sW1[6 * HID];
    __shared__ float sb1[HID];
    __shared__ float sW2[HID * ODIM];   // 32 KB
    __shared__ float sb2[ODIM];
    __shared__ float s_stats[2][6];
    __shared__ float s_h[2][HID];

    const int tid = threadIdx.x;
    for (int i = tid; i < 6 * HID;    i += 256) sW1[i] = W1[i];
    for (int i = tid; i < HID;        i += 256) sb1[i] = b1[i];
    for (int i = tid; i < HID * ODIM; i += 256) sW2[i] = W2[i];
    for (int i = tid; i < ODIM;       i += 256) sb2[i] = b2[i];
    __syncthreads();

    const int half = tid >> 7;     // 0 or 1
    const int lt   = tid & 127;    // 0..127
    const int ROWS = BB * FF;
    const int rowsPerBlock = ROWS / gridDim.x;
    const int base = blockIdx.x * rowsPerBlock;

    for (int i = 0; i < rowsPerBlock; i += 2) {
        const int r = base + i + half;
        if (lt < 6) s_stats[half][lt] = g_stats[(size_t)r * 6 + lt];
        __syncthreads();
        if (lt < HID) {
            float a = sb1[lt];
#pragma unroll
            for (int k = 0; k < 6; k++) a += s_stats[half][k] * sW1[k * HID + lt];
            s_h[half][lt] = 0.5f * a * (1.0f + erff(a * 0.70710678118654752f));
        }
        __syncthreads();
        {
            float o = sb2[lt];
#pragma unroll
            for (int j = 0; j < HID; j++) o += s_h[half][j] * sW2[j * ODIM + lt];
            out[(size_t)r * ODIM + lt] = o;
        }
        __syncthreads();
    }
}

// ---------------------------------------------------------------------------
extern "C" void kernel_launch(void* const* d_in, const int* in_sizes, int n_in,
                              void* d_out, int out_size) {
    const float*     X  = (const float*)d_in[0];       // [64, 4096, 256] f32
    const long long* y  = (const long long*)d_in[1];   // [64, 4096] i64
    const float*     W1 = (const float*)d_in[2];       // [6, 64]
    const float*     b1 = (const float*)d_in[3];       // [64]
    const float*     W2 = (const float*)d_in[4];       // [64, 128]
    const float*     b2 = (const float*)d_in[5];       // [128]
    float* out = (float*)d_out;                        // [64, 256, 128]

    dim3 tgrid(FF / 32, NN / 32, BB);
    transpose_kernel<<<tgrid, dim3(32, 8)>>>(X);

    dim3 sgrid(FF, BB);
    stats_kernel<<<sgrid, 256>>>(y);

    mlp_kernel<<<256, 256>>>(W1, b1, W2, b2, out);
}

// round 5
// speedup vs baseline: 1.3331x; 1.3331x over previous
#include <cuda_runtime.h>
#include <math.h>

// Problem dims (fixed by setup_inputs)
#define BB 64
#define NN 4096
#define FF 256
#define NCLS 10
#define HID 64
#define ODIM 128

#define HASH_SZ 8192
#define HASH_MASK 8191
#define EMPTY_SLOT 0xFFFFFFFFu

// Scratch
__device__ float g_xt[(size_t)BB * FF * NN];        // 256 MB transposed X [B,F,N]
__device__ float g_stats[(size_t)BB * FF * 6];
__device__ unsigned char g_lab[(size_t)BB * NN];    // labels as u8 (clamped)
__device__ float g_cnt[BB * NCLS];                  // per-batch class counts

// ---------------------------------------------------------------------------
// Kernel A: transpose X [B, N, F] -> g_xt [B, F, N], coalesced both ways.
// ---------------------------------------------------------------------------
__global__ void __launch_bounds__(256) transpose_kernel(const float* __restrict__ X) {
    __shared__ float tile[32][33];
    const int b  = blockIdx.z;
    const int f0 = blockIdx.x * 32;
    const int n0 = blockIdx.y * 32;
    const int tx = threadIdx.x;   // 0..31
    const int ty = threadIdx.y;   // 0..7

    const float* Xb  = X    + (size_t)b * NN * FF;
    float*       Xtb = g_xt + (size_t)b * FF * NN;

#pragma unroll
    for (int k = 0; k < 4; k++)
        tile[ty + k * 8][tx] = Xb[(size_t)(n0 + ty + k * 8) * FF + (f0 + tx)];
    __syncthreads();
#pragma unroll
    for (int k = 0; k < 4; k++)
        Xtb[(size_t)(f0 + ty + k * 8) * NN + (n0 + tx)] = tile[tx][ty + k * 8];
}

// ---------------------------------------------------------------------------
// Kernel P: labels i64 -> u8 (clamped to [0, NCLS)) + per-batch class counts.
// ---------------------------------------------------------------------------
__global__ void __launch_bounds__(256) prep_kernel(const long long* __restrict__ y) {
    const int b = blockIdx.x;
    __shared__ int s_cnt[NCLS];
    const int tid = threadIdx.x;
    if (tid < NCLS) s_cnt[tid] = 0;
    __syncthreads();
    for (int i = tid; i < NN; i += 256) {
        int lab = (int)y[(size_t)b * NN + i];
        lab = lab < 0 ? 0 : (lab >= NCLS ? NCLS - 1 : lab);   // defensive clamp
        g_lab[(size_t)b * NN + i] = (unsigned char)lab;
        atomicAdd(&s_cnt[lab], 1);
    }
    __syncthreads();
    if (tid < NCLS) g_cnt[b * NCLS + tid] = (float)s_cnt[tid];
}

// ---------------------------------------------------------------------------
// Kernel B: per-(b,f) column statistics. One 256-thread CTA per column.
// Vectorized coalesced loads; shuffle-tree reductions; exact distinct count
// via shared hash set with read-first probing (CAS only on observed EMPTY).
// ---------------------------------------------------------------------------
__device__ __forceinline__ float warp_sum(float v) {
#pragma unroll
    for (int o = 16; o > 0; o >>= 1) v += __shfl_down_sync(0xffffffffu, v, o);
    return v;
}
__device__ __forceinline__ float warp_max(float v) {
#pragma unroll
    for (int o = 16; o > 0; o >>= 1) v = fmaxf(v, __shfl_down_sync(0xffffffffu, v, o));
    return v;
}

__global__ void __launch_bounds__(256) stats_kernel() {
    const int f = blockIdx.x;
    const int b = blockIdx.y;
    const uint4*  col4 = (const uint4*) (g_xt  + ((size_t)b * FF + f) * NN);
    const uchar4* lab4 = (const uchar4*)(g_lab + (size_t)b * NN);

    __shared__ unsigned s_hash[HASH_SZ];       // 32 KB
    __shared__ float    s_part[16][8];
    __shared__ float    s_final[16];

    const int tid = threadIdx.x;
    for (int i = tid; i < HASH_SZ; i += 256) s_hash[i] = EMPTY_SLOT;
    __syncthreads();

    // ---- pass 1: coalesced 16B/lane loads, moments + class sums ----------
    unsigned bits[16];
    float vsum = 0.f, vsq = 0.f, vabs = 0.f, vmax = 0.f, nanc = 0.f;
    float csum[NCLS];
#pragma unroll
    for (int c = 0; c < NCLS; c++) csum[c] = 0.f;

#pragma unroll
    for (int c = 0; c < 4; c++) {
        const uint4  u = col4[c * 256 + tid];
        const uchar4 l = lab4[c * 256 + tid];
        const unsigned ub[4] = {u.x, u.y, u.z, u.w};
        const int      lb[4] = {l.x, l.y, l.z, l.w};
#pragma unroll
        for (int j = 0; j < 4; j++) {
            float x = __uint_as_float(ub[j]);
            if (isnan(x)) { nanc += 1.f; x = 0.f; }
            bits[c * 4 + j] = (x == 0.0f) ? 0u : __float_as_uint(x);  // canon -0/NaN
            const float ax = fabsf(x);
            vsum += x; vsq += x * x; vabs += ax; vmax = fmaxf(vmax, ax);
            const int lab = lb[j];
#pragma unroll
            for (int cc = 0; cc < NCLS; cc++)
                if (lab == cc) csum[cc] += x;
        }
    }

    // ---- pass 2: distinct count, read-first hash-set insertion -----------
    float uniq = 0.f;
#pragma unroll
    for (int e = 0; e < 16; e++) {
        const unsigned v = bits[e];
        unsigned h = (v * 2654435761u) >> 19;   // top 13 bits -> [0, 8192)
        for (;;) {
            const unsigned cur = s_hash[h];
            if (cur == v) break;                // already present
            if (cur == EMPTY_SLOT) {
                const unsigned old = atomicCAS(&s_hash[h], EMPTY_SLOT, v);
                if (old == EMPTY_SLOT) { uniq += 1.f; break; }
                if (old == v) break;
                // lost race to a different value: fall through, probe on
            }
            h = (h + 1) & HASH_MASK;
        }
    }

    // ---- block reduction of 16 quantities ---------------------------------
    float vals[16];
    vals[0] = vsum; vals[1] = vsq; vals[2] = vabs; vals[3] = vmax;
    vals[4] = nanc; vals[5] = uniq;
#pragma unroll
    for (int c = 0; c < NCLS; c++) vals[6 + c] = csum[c];

    const int lane = tid & 31, w = tid >> 5;
#pragma unroll
    for (int q = 0; q < 16; q++) {
        const float r = (q == 3) ? warp_max(vals[q]) : warp_sum(vals[q]);
        if (lane == 0) s_part[q][w] = r;
    }
    __syncthreads();
    if (tid < 16) {
        float r = s_part[tid][0];
#pragma unroll
        for (int ww = 1; ww < 8; ww++)
            r = (tid == 3) ? fmaxf(r, s_part[tid][ww]) : (r + s_part[tid][ww]);
        s_final[tid] = r;
    }
    __syncthreads();

    if (tid == 0) {
        const float invN = 1.0f / (float)NN;
        const float mean     = s_final[0] * invN;
        const float variance = fmaxf(s_final[1] * invN - mean * mean, 0.0f);
        const float mean_abs = s_final[2] * invN;
        const float maxabs   = s_final[3];
        const float miss     = s_final[4] * invN;
        const float uratio   = s_final[5] * invN;

        float bv = 0.f;
#pragma unroll
        for (int c = 0; c < NCLS; c++) {
            const float cnt = g_cnt[b * NCLS + c];
            const float cm  = s_final[6 + c] / fmaxf(cnt, 1.0f);
            const float d   = cm - mean;
            bv += cnt * d * d;
        }
        bv *= invN;                                   // counts.sum == N
        const float ts = bv / fmaxf(variance, 1e-6f);

        float st[6] = {ts, miss, uratio, variance, mean_abs, maxabs};
        float* o = g_stats + ((size_t)b * FF + f) * 6;
#pragma unroll
        for (int k = 0; k < 6; k++) o[k] = isfinite(st[k]) ? st[k] : 0.0f;
    }
}

// ---------------------------------------------------------------------------
// Kernel C: MLP  out = gelu(stats @ W1 + b1) @ W2 + b2, per (b,f) row.
// ---------------------------------------------------------------------------
__global__ void __launch_bounds__(256) mlp_kernel(
    const float* __restrict__ W1, const float* __restrict__ b1,
    const float* __restrict__ W2, const float* __restrict__ b2,
    float* __restrict__ out)
{
    __shared__ float sW1[6 * HID];
    __shared__ float sb1[HID];
    __shared__ float sW2[HID * ODIM];   // 32 KB
    __shared__ float sb2[ODIM];
    __shared__ float s_stats[2][6];
    __shared__ float s_h[2][HID];

    const int tid = threadIdx.x;
    for (int i = tid; i < 6 * HID;    i += 256) sW1[i] = W1[i];
    for (int i = tid; i < HID;        i += 256) sb1[i] = b1[i];
    for (int i = tid; i < HID * ODIM; i += 256) sW2[i] = W2[i];
    for (int i = tid; i < ODIM;       i += 256) sb2[i] = b2[i];
    __syncthreads();

    const int half = tid >> 7;     // 0 or 1
    const int lt   = tid & 127;    // 0..127
    const int ROWS = BB * FF;
    const int rowsPerBlock = ROWS / gridDim.x;
    const int base = blockIdx.x * rowsPerBlock;

    for (int i = 0; i < rowsPerBlock; i += 2) {
        const int r = base + i + half;
        if (lt < 6) s_stats[half][lt] = g_stats[(size_t)r * 6 + lt];
        __syncthreads();
        if (lt < HID) {
            float a = sb1[lt];
#pragma unroll
            for (int k = 0; k < 6; k++) a += s_stats[half][k] * sW1[k * HID + lt];
            s_h[half][lt] = 0.5f * a * (1.0f + erff(a * 0.70710678118654752f));
        }
        __syncthreads();
        {
            float o = sb2[lt];
#pragma unroll
            for (int j = 0; j < HID; j++) o += s_h[half][j] * sW2[j * ODIM + lt];
            out[(size_t)r * ODIM + lt] = o;
        }
        __syncthreads();
    }
}

// ---------------------------------------------------------------------------
extern "C" void kernel_launch(void* const* d_in, const int* in_sizes, int n_in,
                              void* d_out, int out_size) {
    const float*     X  = (const float*)d_in[0];       // [64, 4096, 256] f32
    const long long* y  = (const long long*)d_in[1];   // [64, 4096] i64
    const float*     W1 = (const float*)d_in[2];       // [6, 64]
    const float*     b1 = (const float*)d_in[3];       // [64]
    const float*     W2 = (const float*)d_in[4];       // [64, 128]
    const float*     b2 = (const float*)d_in[5];       // [128]
    float* out = (float*)d_out;                        // [64, 256, 128]

    dim3 tgrid(FF / 32, NN / 32, BB);
    transpose_kernel<<<tgrid, dim3(32, 8)>>>(X);

    prep_kernel<<<BB, 256>>>(y);

    dim3 sgrid(FF, BB);
    stats_kernel<<<sgrid, 256>>>();

    mlp_kernel<<<256, 256>>>(W1, b1, W2, b2, out);
}

// round 6
// speedup vs baseline: 2.1392x; 1.6047x over previous
#include <cuda_runtime.h>
#include <math.h>

// Problem dims (fixed by setup_inputs)
#define BB 64
#define NN 4096
#define FF 256
#define NCLS 10
#define HID 64
#define ODIM 128

#define HASH_SZ 8192
#define HASH_MASK 8191
#define EMPTY_SLOT 0xFFFFFFFFu

// Scratch
__device__ float g_xt[(size_t)BB * FF * NN];   // 256 MB transposed, NaN-cleaned, class-sorted
__device__ int   g_perm[BB * NN];              // stable class-sort permutation
__device__ float g_nan[BB * FF];               // per-(b,f) NaN counts
__device__ float g_stats[BB * FF * 6];
__device__ float g_cnt[BB * NCLS];             // per-batch class counts
__device__ int   g_off[BB * (NCLS + 1)];       // per-batch class offsets

// ---------------------------------------------------------------------------
// Kernel P: stable counting sort of rows by label (one CTA per batch).
// Also zeroes g_nan and emits class counts/offsets. No atomics, deterministic.
// ---------------------------------------------------------------------------
__global__ void __launch_bounds__(256) prep_kernel(const long long* __restrict__ y) {
    const int b = blockIdx.x, t = threadIdx.x;
    __shared__ int s_mat[NCLS][256];
    __shared__ int s_tot[NCLS];
    __shared__ int s_off[NCLS + 1];

    const long long* yb = y + (size_t)b * NN;
    int lab[16];
    int cnt[NCLS];
#pragma unroll
    for (int c = 0; c < NCLS; c++) cnt[c] = 0;
#pragma unroll
    for (int j = 0; j < 16; j++) {
        int l = (int)yb[t * 16 + j];
        l = l < 0 ? 0 : (l >= NCLS ? NCLS - 1 : l);
        lab[j] = l;
#pragma unroll
        for (int c = 0; c < NCLS; c++) cnt[c] += (l == c);
    }
#pragma unroll
    for (int c = 0; c < NCLS; c++) s_mat[c][t] = cnt[c];
    g_nan[b * FF + t] = 0.f;      // FF == 256
    __syncthreads();

    if (t < NCLS) {               // exclusive scan over 256 thread-counts of class t
        int run = 0;
        for (int i = 0; i < 256; i++) { int v = s_mat[t][i]; s_mat[t][i] = run; run += v; }
        s_tot[t] = run;
        g_cnt[b * NCLS + t] = (float)run;
    }
    __syncthreads();
    if (t == 0) {
        int acc = 0;
#pragma unroll
        for (int c = 0; c < NCLS; c++) { s_off[c] = acc; acc += s_tot[c]; }
        s_off[NCLS] = acc;
#pragma unroll
        for (int c = 0; c <= NCLS; c++) g_off[b * (NCLS + 1) + c] = s_off[c];
    }
    __syncthreads();
#pragma unroll
    for (int c = 0; c < NCLS; c++) s_mat[c][t] += s_off[c];   // start pos per (class, thread)
#pragma unroll
    for (int j = 0; j < 16; j++) {
        const int c = lab[j];
        const int pos = s_mat[c][t]++;     // owner-only update, stable by construction
        g_perm[b * NN + pos] = t * 16 + j;
    }
}

// ---------------------------------------------------------------------------
// Kernel A: gather-transpose X[b][perm[n]][f] -> g_xt[b][f][n], NaN-clean,
// and count NaNs per (b,f) via ballot + rare atomicAdd.
// ---------------------------------------------------------------------------
__global__ void __launch_bounds__(256) transpose_kernel(const float* __restrict__ X) {
    __shared__ float tile[32][33];
    __shared__ unsigned nanmask[32];
    const int b  = blockIdx.z;
    const int f0 = blockIdx.x * 32;
    const int n0 = blockIdx.y * 32;
    const int tx = threadIdx.x;   // 0..31
    const int ty = threadIdx.y;   // 0..7

    const float* Xb  = X    + (size_t)b * NN * FF;
    float*       Xtb = g_xt + (size_t)b * FF * NN;
    const int*   pb  = g_perm + b * NN;

#pragma unroll
    for (int k = 0; k < 4; k++) {
        const int r   = ty + k * 8;
        const int src = pb[n0 + r];                     // uniform per warp
        const float x = Xb[(size_t)src * FF + f0 + tx]; // 128B coalesced
        const bool bad = isnan(x);
        const unsigned m = __ballot_sync(0xffffffffu, bad);
        if (tx == 0) nanmask[r] = m;
        tile[r][tx] = bad ? 0.f : x;
    }
    __syncthreads();
#pragma unroll
    for (int k = 0; k < 4; k++) {
        const int c = ty + k * 8;                       // feature col within tile
        Xtb[(size_t)(f0 + c) * NN + n0 + tx] = tile[tx][c];
        const unsigned flag = (nanmask[tx] >> c) & 1u;
        const unsigned bal = __ballot_sync(0xffffffffu, flag);
        if (tx == 0 && bal) atomicAdd(&g_nan[b * FF + f0 + c], (float)__popc(bal));
    }
}

// ---------------------------------------------------------------------------
// Kernel B: per-(b,f) column statistics. Data is clean and class-sorted.
// Class sums = prefix differences at class boundaries (deterministic scan).
// Distinct count: bounded racy-STS hash rounds + bounded-CAS exact fallback,
// counted by occupied-slot scan.
// ---------------------------------------------------------------------------
__device__ __forceinline__ float warp_sum(float v) {
#pragma unroll
    for (int o = 16; o > 0; o >>= 1) v += __shfl_down_sync(0xffffffffu, v, o);
    return v;
}
__device__ __forceinline__ float warp_max(float v) {
#pragma unroll
    for (int o = 16; o > 0; o >>= 1) v = fmaxf(v, __shfl_down_sync(0xffffffffu, v, o));
    return v;
}

__global__ void __launch_bounds__(256) stats_kernel() {
    const int f = blockIdx.x;
    const int b = blockIdx.y;
    const float4* col4 = (const float4*)(g_xt + ((size_t)b * FF + f) * NN);

    __shared__ unsigned s_hash[HASH_SZ];     // 32 KB
    __shared__ int      s_offs[NCLS + 1];
    __shared__ float    s_bound[NCLS + 1];
    __shared__ float    s_wsum[8];
    __shared__ float    s_part[4][8];
    __shared__ float    s_final[4];

    const int tid  = threadIdx.x;
    const int lane = tid & 31, w = tid >> 5;
    const int p0   = tid * 16;

    if (tid <= NCLS) s_offs[tid] = g_off[b * (NCLS + 1) + tid];
    for (int i = tid; i < HASH_SZ; i += 256) s_hash[i] = EMPTY_SLOT;
    __syncthreads();

    // ---- load 16 contiguous values, moments ------------------------------
    unsigned bits[16];
    float vsum = 0.f, vsq = 0.f, vabs = 0.f, vmax = 0.f;
#pragma unroll
    for (int q = 0; q < 4; q++) {
        const float4 a = col4[tid * 4 + q];
        const float xs[4] = {a.x, a.y, a.z, a.w};
#pragma unroll
        for (int j = 0; j < 4; j++) {
            const float x = xs[j];
            bits[q * 4 + j] = (x == 0.0f) ? 0u : __float_as_uint(x);  // canon -0
            const float ax = fabsf(x);
            vsum += x; vsq = fmaf(x, x, vsq); vabs += ax; vmax = fmaxf(vmax, ax);
        }
    }

    // ---- deterministic block exclusive scan of per-thread sums -----------
    float inc = vsum;
#pragma unroll
    for (int o = 1; o < 32; o <<= 1) {
        const float nb = __shfl_up_sync(0xffffffffu, inc, o);
        if (lane >= o) inc += nb;
    }
    if (lane == 31) s_wsum[w] = inc;
    __syncthreads();
    if (w == 0) {
        float v = (lane < 8) ? s_wsum[lane] : 0.f;
#pragma unroll
        for (int o = 1; o < 8; o <<= 1) {
            const float nb = __shfl_up_sync(0xffffffffu, v, o);
            if (lane >= o) v += nb;
        }
        if (lane < 8) s_wsum[lane] = v;   // inclusive warp prefixes
    }
    __syncthreads();
    const float total = s_wsum[7];
    const float excl  = inc - vsum + (w ? s_wsum[w - 1] : 0.f);

    // ---- class-boundary prefix values (unique owner per boundary) --------
#pragma unroll
    for (int c = 1; c <= NCLS; c++) {
        const int q = s_offs[c];
        if (q > p0 && q <= p0 + 16) {
            const int idx = q - p0;       // 1..16
            float part = 0.f;
#pragma unroll
            for (int j = 0; j < 16; j++)
                if (j < idx) part += __uint_as_float(bits[j]);
            s_bound[c] = excl + part;
        }
    }
    if (tid == 0) {
#pragma unroll
        for (int c = 0; c <= NCLS; c++)
            if (s_offs[c] == 0) s_bound[c] = 0.f;
    }

    // ---- distinct count: racy-STS rounds (bounded) ------------------------
    volatile unsigned* vh = s_hash;
    unsigned slotv[16];
#pragma unroll
    for (int e = 0; e < 16; e++) slotv[e] = (bits[e] * 2654435761u) >> 19;

    unsigned pend = 0xFFFFu;
    for (int r = 0; r < 32; ++r) {
        if (__syncthreads_count(pend) == 0) break;   // uniform; orders prior writes
        if (pend) {
#pragma unroll
            for (int e = 0; e < 16; e++) {
                if (pend & (1u << e)) {
                    const unsigned cur = vh[slotv[e]];
                    if (cur == bits[e]) {
                        pend &= ~(1u << e);           // my value is in the table
                    } else if (cur == EMPTY_SLOT) {
                        vh[slotv[e]] = bits[e];       // claim; verify next round
                    } else {
                        slotv[e] = (slotv[e] + 1) & HASH_MASK;
                    }
                }
            }
        }
    }
    if (pend) {   // exact bounded fallback (rarely taken)
#pragma unroll
        for (int e = 0; e < 16; e++) {
            if (pend & (1u << e)) {
                unsigned h = slotv[e];
                for (int s = 0; s < HASH_SZ; s++) {
                    const unsigned old = atomicCAS(&s_hash[h], EMPTY_SLOT, bits[e]);
                    if (old == EMPTY_SLOT || old == bits[e]) break;
                    h = (h + 1) & HASH_MASK;
                }
            }
        }
    }
    __syncthreads();   // hash final + s_bound visible

    float occ = 0.f;
#pragma unroll
    for (int i = 0; i < HASH_SZ / 256; i++)
        occ += (s_hash[i * 256 + tid] != EMPTY_SLOT) ? 1.f : 0.f;

    // ---- block reduction of {vsq, vabs, vmax, occ} -------------------------
    float vals[4] = {vsq, vabs, vmax, occ};
#pragma unroll
    for (int q = 0; q < 4; q++) {
        const float r = (q == 2) ? warp_max(vals[q]) : warp_sum(vals[q]);
        if (lane == 0) s_part[q][w] = r;
    }
    __syncthreads();
    if (tid < 4) {
        float r = s_part[tid][0];
#pragma unroll
        for (int ww = 1; ww < 8; ww++)
            r = (tid == 2) ? fmaxf(r, s_part[tid][ww]) : (r + s_part[tid][ww]);
        s_final[tid] = r;
    }
    __syncthreads();

    if (tid == 0) {
        const float invN = 1.0f / (float)NN;
        const float mean     = total * invN;
        const float variance = fmaxf(s_final[0] * invN - mean * mean, 0.0f);
        const float mean_abs = s_final[1] * invN;
        const float maxabs   = s_final[2];
        const float uratio   = s_final[3] * invN;
        const float miss     = g_nan[b * FF + f] * invN;

        float bv = 0.f;
#pragma unroll
        for (int c = 0; c < NCLS; c++) {
            const float cnt = g_cnt[b * NCLS + c];
            const float cs  = s_bound[c + 1] - s_bound[c];
            const float cm  = cs / fmaxf(cnt, 1.0f);
            const float d   = cm - mean;
            bv += cnt * d * d;
        }
        bv *= invN;
        const float ts = bv / fmaxf(variance, 1e-6f);

        float st[6] = {ts, miss, uratio, variance, mean_abs, maxabs};
        float* o = g_stats + ((size_t)b * FF + f) * 6;
#pragma unroll
        for (int k = 0; k < 6; k++) o[k] = isfinite(st[k]) ? st[k] : 0.0f;
    }
}

// ---------------------------------------------------------------------------
// Kernel C: MLP  out = gelu(stats @ W1 + b1) @ W2 + b2, per (b,f) row.
// ---------------------------------------------------------------------------
__global__ void __launch_bounds__(256) mlp_kernel(
    const float* __restrict__ W1, const float* __restrict__ b1,
    const float* __restrict__ W2, const float* __restrict__ b2,
    float* __restrict__ out)
{
    __shared__ float sW1[6 * HID];
    __shared__ float sb1[HID];
    __shared__ float sW2[HID * ODIM];   // 32 KB
    __shared__ float sb2[ODIM];
    __shared__ float s_stats[2][6];
    __shared__ float s_h[2][HID];

    const int tid = threadIdx.x;
    for (int i = tid; i < 6 * HID;    i += 256) sW1[i] = W1[i];
    for (int i = tid; i < HID;        i += 256) sb1[i] = b1[i];
    for (int i = tid; i < HID * ODIM; i += 256) sW2[i] = W2[i];
    for (int i = tid; i < ODIM;       i += 256) sb2[i] = b2[i];
    __syncthreads();

    const int half = tid >> 7;
    const int lt   = tid & 127;
    const int ROWS = BB * FF;
    const int rowsPerBlock = ROWS / gridDim.x;
    const int base = blockIdx.x * rowsPerBlock;

    for (int i = 0; i < rowsPerBlock; i += 2) {
        const int r = base + i + half;
        if (lt < 6) s_stats[half][lt] = g_stats[(size_t)r * 6 + lt];
        __syncthreads();
        if (lt < HID) {
            float a = sb1[lt];
#pragma unroll
            for (int k = 0; k < 6; k++) a += s_stats[half][k] * sW1[k * HID + lt];
            s_h[half][lt] = 0.5f * a * (1.0f + erff(a * 0.70710678118654752f));
        }
        __syncthreads();
        {
            float o = sb2[lt];
#pragma unroll
            for (int j = 0; j < HID; j++) o += s_h[half][j] * sW2[j * ODIM + lt];
            out[(size_t)r * ODIM + lt] = o;
        }
        __syncthreads();
    }
}

// ---------------------------------------------------------------------------
extern "C" void kernel_launch(void* const* d_in, const int* in_sizes, int n_in,
                              void* d_out, int out_size) {
    const float*     X  = (const float*)d_in[0];       // [64, 4096, 256] f32
    const long long* y  = (const long long*)d_in[1];   // [64, 4096] i64
    const float*     W1 = (const float*)d_in[2];       // [6, 64]
    const float*     b1 = (const float*)d_in[3];       // [64]
    const float*     W2 = (const float*)d_in[4];       // [64, 128]
    const float*     b2 = (const float*)d_in[5];       // [128]
    float* out = (float*)d_out;                        // [64, 256, 128]

    prep_kernel<<<BB, 256>>>(y);

    dim3 tgrid(FF / 32, NN / 32, BB);
    transpose_kernel<<<tgrid, dim3(32, 8)>>>(X);

    dim3 sgrid(FF, BB);
    stats_kernel<<<sgrid, 256>>>();

    mlp_kernel<<<512, 256>>>(W1, b1, W2, b2, out);
}

// round 7
// speedup vs baseline: 2.3957x; 1.1199x over previous
#include <cuda_runtime.h>
#include <math.h>

// Problem dims (fixed by setup_inputs)
#define BB 64
#define NN 4096
#define FF 256
#define NCLS 10
#define HID 64
#define ODIM 128

#define HASH_SZ 8192
#define HASH_MASK 8191
#define EMPTY_SLOT 0xFFFFFFFFu

// Scratch
__device__ float g_xt[(size_t)BB * FF * NN];   // 256 MB transposed, NaN-cleaned, class-sorted
__device__ int   g_perm[BB * NN];              // stable class-sort permutation
__device__ float g_nan[BB * FF];               // per-(b,f) NaN counts
__device__ float g_stats[BB * FF * 6];
__device__ float g_cnt[BB * NCLS];             // per-batch class counts
__device__ int   g_off[BB * (NCLS + 1)];       // per-batch class offsets

// ---------------------------------------------------------------------------
// Kernel P: stable counting sort of rows by label (one CTA per batch).
// ---------------------------------------------------------------------------
__global__ void __launch_bounds__(256) prep_kernel(const long long* __restrict__ y) {
    const int b = blockIdx.x, t = threadIdx.x;
    __shared__ int s_mat[NCLS][256];
    __shared__ int s_tot[NCLS];
    __shared__ int s_off[NCLS + 1];

    const long long* yb = y + (size_t)b * NN;
    int lab[16];
    int cnt[NCLS];
#pragma unroll
    for (int c = 0; c < NCLS; c++) cnt[c] = 0;
#pragma unroll
    for (int j = 0; j < 16; j++) {
        int l = (int)yb[t * 16 + j];
        l = l < 0 ? 0 : (l >= NCLS ? NCLS - 1 : l);
        lab[j] = l;
#pragma unroll
        for (int c = 0; c < NCLS; c++) cnt[c] += (l == c);
    }
#pragma unroll
    for (int c = 0; c < NCLS; c++) s_mat[c][t] = cnt[c];
    g_nan[b * FF + t] = 0.f;      // FF == 256
    __syncthreads();

    if (t < NCLS) {               // exclusive scan over 256 thread-counts of class t
        int run = 0;
        for (int i = 0; i < 256; i++) { int v = s_mat[t][i]; s_mat[t][i] = run; run += v; }
        s_tot[t] = run;
        g_cnt[b * NCLS + t] = (float)run;
    }
    __syncthreads();
    if (t == 0) {
        int acc = 0;
#pragma unroll
        for (int c = 0; c < NCLS; c++) { s_off[c] = acc; acc += s_tot[c]; }
        s_off[NCLS] = acc;
#pragma unroll
        for (int c = 0; c <= NCLS; c++) g_off[b * (NCLS + 1) + c] = s_off[c];
    }
    __syncthreads();
#pragma unroll
    for (int c = 0; c < NCLS; c++) s_mat[c][t] += s_off[c];
#pragma unroll
    for (int j = 0; j < 16; j++) {
        const int c = lab[j];
        const int pos = s_mat[c][t]++;     // owner-only update, stable by construction
        g_perm[b * NN + pos] = t * 16 + j;
    }
}

// ---------------------------------------------------------------------------
// Kernel A: gather-transpose X[b][perm[n]][f] -> g_xt[b][f][n], NaN-clean,
// and count NaNs per (b,f) via ballot + rare atomicAdd.
// ---------------------------------------------------------------------------
__global__ void __launch_bounds__(256) transpose_kernel(const float* __restrict__ X) {
    __shared__ float tile[32][33];
    __shared__ unsigned nanmask[32];
    const int b  = blockIdx.z;
    const int f0 = blockIdx.x * 32;
    const int n0 = blockIdx.y * 32;
    const int tx = threadIdx.x;   // 0..31
    const int ty = threadIdx.y;   // 0..7

    const float* Xb  = X    + (size_t)b * NN * FF;
    float*       Xtb = g_xt + (size_t)b * FF * NN;
    const int*   pb  = g_perm + b * NN;

#pragma unroll
    for (int k = 0; k < 4; k++) {
        const int r   = ty + k * 8;
        const int src = pb[n0 + r];                     // uniform per warp
        const float x = Xb[(size_t)src * FF + f0 + tx]; // 128B coalesced
        const bool bad = isnan(x);
        const unsigned m = __ballot_sync(0xffffffffu, bad);
        if (tx == 0) nanmask[r] = m;
        tile[r][tx] = bad ? 0.f : x;
    }
    __syncthreads();
#pragma unroll
    for (int k = 0; k < 4; k++) {
        const int c = ty + k * 8;
        Xtb[(size_t)(f0 + c) * NN + n0 + tx] = tile[tx][c];
        const unsigned flag = (nanmask[tx] >> c) & 1u;
        const unsigned bal = __ballot_sync(0xffffffffu, flag);
        if (tx == 0 && bal) atomicAdd(&g_nan[b * FF + f0 + c], (float)__popc(bal));
    }
}

// ---------------------------------------------------------------------------
// Kernel B: per-(b,f) column statistics on clean, class-sorted data.
// Distinct count: chase-within-round racy hash (claim by plain STS, verify
// after barrier; slots immutable once a writing round ends) + CAS fallback.
// ---------------------------------------------------------------------------
__device__ __forceinline__ float warp_sum(float v) {
#pragma unroll
    for (int o = 16; o > 0; o >>= 1) v += __shfl_down_sync(0xffffffffu, v, o);
    return v;
}
__device__ __forceinline__ float warp_max(float v) {
#pragma unroll
    for (int o = 16; o > 0; o >>= 1) v = fmaxf(v, __shfl_down_sync(0xffffffffu, v, o));
    return v;
}

__global__ void __launch_bounds__(256) stats_kernel() {
    const int f = blockIdx.x;
    const int b = blockIdx.y;
    const float4* col4 = (const float4*)(g_xt + ((size_t)b * FF + f) * NN);

    __shared__ unsigned s_hash[HASH_SZ];     // 32 KB
    __shared__ int      s_offs[NCLS + 1];
    __shared__ float    s_bound[NCLS + 1];
    __shared__ float    s_wsum[8];
    __shared__ float    s_part[4][8];
    __shared__ float    s_final[4];

    const int tid  = threadIdx.x;
    const int lane = tid & 31, w = tid >> 5;
    const int p0   = tid * 16;

    if (tid <= NCLS) s_offs[tid] = g_off[b * (NCLS + 1) + tid];
    for (int i = tid; i < HASH_SZ; i += 256) s_hash[i] = EMPTY_SLOT;
    __syncthreads();

    // ---- load 16 contiguous values, moments ------------------------------
    unsigned bits[16];
    float vsum = 0.f, vsq = 0.f, vabs = 0.f, vmax = 0.f;
#pragma unroll
    for (int q = 0; q < 4; q++) {
        const float4 a = col4[tid * 4 + q];
        const float xs[4] = {a.x, a.y, a.z, a.w};
#pragma unroll
        for (int j = 0; j < 4; j++) {
            const float x = xs[j];
            bits[q * 4 + j] = (x == 0.0f) ? 0u : __float_as_uint(x);  // canon -0
            const float ax = fabsf(x);
            vsum += x; vsq = fmaf(x, x, vsq); vabs += ax; vmax = fmaxf(vmax, ax);
        }
    }

    // ---- deterministic block exclusive scan of per-thread sums -----------
    float inc = vsum;
#pragma unroll
    for (int o = 1; o < 32; o <<= 1) {
        const float nb = __shfl_up_sync(0xffffffffu, inc, o);
        if (lane >= o) inc += nb;
    }
    if (lane == 31) s_wsum[w] = inc;
    __syncthreads();
    if (w == 0) {
        float v = (lane < 8) ? s_wsum[lane] : 0.f;
#pragma unroll
        for (int o = 1; o < 8; o <<= 1) {
            const float nb = __shfl_up_sync(0xffffffffu, v, o);
            if (lane >= o) v += nb;
        }
        if (lane < 8) s_wsum[lane] = v;   // inclusive warp prefixes
    }
    __syncthreads();
    const float total = s_wsum[7];
    const float excl  = inc - vsum + (w ? s_wsum[w - 1] : 0.f);

    // ---- class-boundary prefix values (unique owner per boundary) --------
#pragma unroll
    for (int c = 1; c <= NCLS; c++) {
        const int q = s_offs[c];
        if (q > p0 && q <= p0 + 16) {
            const int idx = q - p0;       // 1..16
            float part = 0.f;
#pragma unroll
            for (int j = 0; j < 16; j++)
                if (j < idx) part += __uint_as_float(bits[j]);
            s_bound[c] = excl + part;
        }
    }
    if (tid == 0) {
#pragma unroll
        for (int c = 0; c <= NCLS; c++)
            if (s_offs[c] == 0) s_bound[c] = 0.f;
    }

    // ---- distinct count: chase-within-round racy hash --------------------
    volatile unsigned* vh = s_hash;
    unsigned slotv[16];
#pragma unroll
    for (int e = 0; e < 16; e++) slotv[e] = (bits[e] * 2654435761u) >> 19;

    unsigned pend = 0xFFFFu;
    for (int r = 0; r < 16; ++r) {
        if (__syncthreads_count(pend) == 0) break;   // uniform; orders prior writes
        if (pend) {
#pragma unroll
            for (int e = 0; e < 16; e++) {
                if (pend & (1u << e)) {
                    const unsigned v = bits[e];
                    unsigned h = slotv[e];
                    for (int s = 0; s < HASH_SZ; s++) {
                        const unsigned cur = vh[h];
                        if (cur == v) { pend &= ~(1u << e); break; }   // settled
                        if (cur == EMPTY_SLOT) { vh[h] = v; break; }   // claim; verify next round
                        h = (h + 1) & HASH_MASK;
                    }
                    slotv[e] = h;
                }
            }
        }
    }
    if (pend) {   // exact bounded fallback (rarely taken)
#pragma unroll
        for (int e = 0; e < 16; e++) {
            if (pend & (1u << e)) {
                unsigned h = slotv[e];
                for (int s = 0; s < HASH_SZ; s++) {
                    const unsigned old = atomicCAS(&s_hash[h], EMPTY_SLOT, bits[e]);
                    if (old == EMPTY_SLOT || old == bits[e]) break;
                    h = (h + 1) & HASH_MASK;
                }
            }
        }
    }
    __syncthreads();   // hash final + s_bound visible

    float occ = 0.f;
#pragma unroll
    for (int i = 0; i < HASH_SZ / 256; i++)
        occ += (s_hash[i * 256 + tid] != EMPTY_SLOT) ? 1.f : 0.f;

    // ---- block reduction of {vsq, vabs, vmax, occ} ------------------------
    float vals[4] = {vsq, vabs, vmax, occ};
#pragma unroll
    for (int q = 0; q < 4; q++) {
        const float r = (q == 2) ? warp_max(vals[q]) : warp_sum(vals[q]);
        if (lane == 0) s_part[q][w] = r;
    }
    __syncthreads();
    if (tid < 4) {
        float r = s_part[tid][0];
#pragma unroll
        for (int ww = 1; ww < 8; ww++)
            r = (tid == 2) ? fmaxf(r, s_part[tid][ww]) : (r + s_part[tid][ww]);
        s_final[tid] = r;
    }
    __syncthreads();

    if (tid == 0) {
        const float invN = 1.0f / (float)NN;
        const float mean     = total * invN;
        const float variance = fmaxf(s_final[0] * invN - mean * mean, 0.0f);
        const float mean_abs = s_final[1] * invN;
        const float maxabs   = s_final[2];
        const float uratio   = s_final[3] * invN;
        const float miss     = g_nan[b * FF + f] * invN;

        float bv = 0.f;
#pragma unroll
        for (int c = 0; c < NCLS; c++) {
            const float cnt = g_cnt[b * NCLS + c];
            const float cs  = s_bound[c + 1] - s_bound[c];
            const float cm  = cs / fmaxf(cnt, 1.0f);
            const float d   = cm - mean;
            bv += cnt * d * d;
        }
        bv *= invN;
        const float ts = bv / fmaxf(variance, 1e-6f);

        float st[6] = {ts, miss, uratio, variance, mean_abs, maxabs};
        float* o = g_stats + ((size_t)b * FF + f) * 6;
#pragma unroll
        for (int k = 0; k < 6; k++) o[k] = isfinite(st[k]) ? st[k] : 0.0f;
    }
}

// ---------------------------------------------------------------------------
// Kernel C: barrier-free MLP. One warp per row: lane computes 2 hidden units
// and 4 outputs; only __syncwarp between stages.
// ---------------------------------------------------------------------------
__global__ void __launch_bounds__(256) mlp_kernel(
    const float* __restrict__ W1, const float* __restrict__ b1,
    const float* __restrict__ W2, const float* __restrict__ b2,
    float* __restrict__ out)
{
    __shared__ float sW1[6 * HID];
    __shared__ float sb1[HID];
    __shared__ float sW2[HID * ODIM];   // 32 KB
    __shared__ float sb2[ODIM];
    __shared__ float s_h[8][HID];       // one row per warp

    const int tid = threadIdx.x;
    for (int i = tid; i < 6 * HID;    i += 256) sW1[i] = W1[i];
    for (int i = tid; i < HID;        i += 256) sb1[i] = b1[i];
    for (int i = tid; i < HID * ODIM; i += 256) sW2[i] = W2[i];
    for (int i = tid; i < ODIM;       i += 256) sb2[i] = b2[i];
    __syncthreads();

    const int lane = tid & 31, w = tid >> 5;
    const int ROWS = BB * FF;
    const int warpsTotal = (gridDim.x * 256) >> 5;
    const int gw = blockIdx.x * 8 + w;

    for (int r = gw; r < ROWS; r += warpsTotal) {
        float st[6];
#pragma unroll
        for (int k = 0; k < 6; k++) st[k] = g_stats[(size_t)r * 6 + k];

#pragma unroll
        for (int hh = 0; hh < 2; hh++) {
            const int j = lane + hh * 32;
            float a = sb1[j];
#pragma unroll
            for (int k = 0; k < 6; k++) a = fmaf(st[k], sW1[k * HID + j], a);
            s_h[w][j] = 0.5f * a * (1.0f + erff(a * 0.70710678118654752f));
        }
        __syncwarp();

#pragma unroll
        for (int oo = 0; oo < 4; oo++) {
            const int j = lane + oo * 32;
            float o = sb2[j];
#pragma unroll
            for (int i = 0; i < HID; i++) o = fmaf(s_h[w][i], sW2[i * ODIM + j], o);
            out[(size_t)r * ODIM + j] = o;
        }
        __syncwarp();
    }
}

// ---------------------------------------------------------------------------
extern "C" void kernel_launch(void* const* d_in, const int* in_sizes, int n_in,
                              void* d_out, int out_size) {
    const float*     X  = (const float*)d_in[0];       // [64, 4096, 256] f32
    const long long* y  = (const long long*)d_in[1];   // [64, 4096] i64
    const float*     W1 = (const float*)d_in[2];       // [6, 64]
    const float*     b1 = (const float*)d_in[3];       // [64]
    const float*     W2 = (const float*)d_in[4];       // [64, 128]
    const float*     b2 = (const float*)d_in[5];       // [128]
    float* out = (float*)d_out;                        // [64, 256, 128]

    prep_kernel<<<BB, 256>>>(y);

    dim3 tgrid(FF / 32, NN / 32, BB);
    transpose_kernel<<<tgrid, dim3(32, 8)>>>(X);

    dim3 sgrid(FF, BB);
    stats_kernel<<<sgrid, 256>>>();

    mlp_kernel<<<512, 256>>>(W1, b1, W2, b2, out);
}